// round 9
// baseline (speedup 1.0000x reference)
#include <cuda_runtime.h>
#include <stdint.h>

#define BATCH 64
#define NA    8400
#define NC    80
#define HF_   160
#define WF_   160
#define KTOP  300
#define FIELD_ELEMS (HF_ * WF_)          // 25600 floats = 102.4 KB
#define POOL_SPLIT 2
#define POOL_THREADS 1024
#define ANCH_PER_BLK (NA / POOL_SPLIT)
#define RESCAN 0xFFFFFFFFu
#define KBASE 0x3E800000u                // bits of 0.25f

#define MULrn(a,b) __fmul_rn((a),(b))
#define ADDrn(a,b) __fadd_rn((a),(b))
#define SUBrn(a,b) __fsub_rn((a),(b))
#define DIVrn(a,b) __fdiv_rn((a),(b))

// Scratch (allocation-free rule: __device__ globals)
__device__ float    g_beta[BATCH * NA];
__device__ float    g_m1[BATCH * NA];
__device__ uint32_t g_cand[BATCH * NA];

// XLA EmitFastTanh (Eigen rational), no fma, clamp +-7.90531110763549805,
// passthrough |x| < 4e-4.
__device__ __forceinline__ float tanh_xla(float x) {
    const float kMax = 7.90531110763549805f;
    float xc = fmaxf(-kMax, fminf(x, kMax));
    float x2 = MULrn(xc, xc);
    float p = -2.76076847742355e-16f;
    p = ADDrn(MULrn(x2, p),  2.00018790482477e-13f);
    p = ADDrn(MULrn(x2, p), -8.60467152213735e-11f);
    p = ADDrn(MULrn(x2, p),  5.12229709037114e-08f);
    p = ADDrn(MULrn(x2, p),  1.48572235717979e-05f);
    p = ADDrn(MULrn(x2, p),  6.37261928875436e-04f);
    p = ADDrn(MULrn(x2, p),  4.89352455891786e-03f);
    float num = MULrn(xc, p);
    float q = 1.19825839466702e-06f;
    q = ADDrn(MULrn(x2, q), 1.18534705686654e-04f);
    q = ADDrn(MULrn(x2, q), 2.26843463243900e-03f);
    q = ADDrn(MULrn(x2, q), 4.89352518554385e-03f);
    float t = DIVrn(num, q);
    return (fabsf(x) < 0.0004f) ? x : t;
}
__device__ __forceinline__ float sigmoid_xla(float x) {
    float th = tanh_xla(MULrn(0.5f, x));
    return ADDrn(0.5f, MULrn(0.5f, th));
}

// ---------------- Kernel 1: box pooling with smem-resident field ------------
__global__ void __launch_bounds__(POOL_THREADS) pool_kernel(
        const float4* __restrict__ boxes,
        const float*  __restrict__ field) {
    extern __shared__ float sf[];
    int b    = blockIdx.x / POOL_SPLIT;
    int half = blockIdx.x % POOL_SPLIT;
    int tid  = threadIdx.x;

    const float4* fsrc = (const float4*)(field + (size_t)b * FIELD_ELEMS);
    float4* fdst = (float4*)sf;
#pragma unroll
    for (int i = tid; i < FIELD_ELEMS / 4; i += POOL_THREADS)
        fdst[i] = __ldg(fsrc + i);
    __syncthreads();

    for (int a = half * ANCH_PER_BLK + tid; a < (half + 1) * ANCH_PER_BLK; a += POOL_THREADS) {
        int anchor = b * NA + a;
        float4 bx = __ldg(boxes + anchor);
        float x1 = bx.x, y1 = bx.y, x2 = bx.z, y2 = bx.w;
        float dx = SUBrn(x2, x1), dy = SUBrn(y2, y1);
        float fu[3], fv[3];
        int u0[3], u1[3], v0[3], v1[3];
#pragma unroll
        for (int j = 0; j < 3; j++) {
            float t  = MULrn((float)j + 0.5f, 1.0f / 3.0f);
            float xs = ADDrn(x1, MULrn(t, dx));
            float ys = ADDrn(y1, MULrn(t, dy));
            float u  = fminf(fmaxf(SUBrn(MULrn(xs, 0.25f), 0.5f), 0.0f), 159.0f);
            float vv = fminf(fmaxf(SUBrn(MULrn(ys, 0.25f), 0.5f), 0.0f), 159.0f);
            float u0f = floorf(u), v0f = floorf(vv);
            fu[j] = SUBrn(u, u0f); fv[j] = SUBrn(vv, v0f);
            u0[j] = (int)u0f; v0[j] = (int)v0f;
            u1[j] = min(u0[j] + 1, WF_ - 1);
            v1[j] = min(v0[j] + 1, HF_ - 1);
        }
        float e[9];
#pragma unroll
        for (int jy = 0; jy < 3; jy++) {
            int r0 = v0[jy] * WF_, r1 = v1[jy] * WF_;
            float wv = fv[jy], omv = SUBrn(1.0f, fv[jy]);
#pragma unroll
            for (int jx = 0; jx < 3; jx++) {
                float wu = fu[jx], omu = SUBrn(1.0f, fu[jx]);
                float f00 = sf[r0 + u0[jx]];
                float f01 = sf[r0 + u1[jx]];
                float f10 = sf[r1 + u0[jx]];
                float f11 = sf[r1 + u1[jx]];
                float t1 = MULrn(MULrn(f00, omv), omu);
                float t2 = MULrn(MULrn(f01, omv), wu);
                float t3 = MULrn(MULrn(f10, wv), omu);
                float t4 = MULrn(MULrn(f11, wv), wu);
                e[jy * 3 + jx] = ADDrn(ADDrn(ADDrn(t1, t2), t3), t4);
            }
        }
        float s_left  = ADDrn(ADDrn(ADDrn(e[0], e[8]), e[4]), ADDrn(e[2], e[6]));
        float s_right = ADDrn(ADDrn(e[1], e[5]), ADDrn(e[3], e[7]));
        float ssum    = ADDrn(s_left, s_right);
        float beta = MULrn(ssum, 1.0f / 9.0f);
        float w = fmaxf(dx, 0.0f), h = fmaxf(dy, 0.0f);
        float area = MULrn(MULrn(w, h), 1.0f / 409600.0f);
        float small = (area < 0.01f) ? 1.0f : 0.0f;
        g_beta[anchor] = MULrn(beta, ADDrn(1.0f, MULrn(0.5f, small)));
    }
}

// ------- Kernel 2: pure-bandwidth class scan (max + plateau candidates) -----
// 4 threads/anchor; beta-free. Writes m1 and a single candidate index, or
// RESCAN flag when >1 logit is within the sigmoid ulp-plateau window of m1.
__global__ void __launch_bounds__(256) scan_kernel(const float4* __restrict__ cls) {
    int gt = blockIdx.x * 256 + threadIdx.x;
    int anchor = gt >> 2;
    int sub = gt & 3;

    const float4* cp = cls + (size_t)anchor * (NC / 4);
    float4 v[5];
#pragma unroll
    for (int q = 0; q < 5; q++) v[q] = __ldg(cp + sub + 4 * q);

    float m_loc = -3.0e38f;
#pragma unroll
    for (int q = 0; q < 5; q++)
        m_loc = fmaxf(m_loc, fmaxf(fmaxf(v[q].x, v[q].y), fmaxf(v[q].z, v[q].w)));
    float m1 = m_loc;
#pragma unroll
    for (int off = 1; off < 4; off <<= 1)
        m1 = fmaxf(m1, __shfl_xor_sync(0xffffffffu, m1, off, 4));

    float thrW = m1 - 3e-4f;
    int cnt = 0, idxm = 0x7fffffff;
#pragma unroll
    for (int q = 0; q < 5; q++) {
        float ev[4] = {v[q].x, v[q].y, v[q].z, v[q].w};
#pragma unroll
        for (int r = 0; r < 4; r++) {
            if (ev[r] > thrW) {
                cnt++;
                int ci = (sub + 4 * q) * 4 + r;
                if (ci < idxm) idxm = ci;
            }
        }
    }
#pragma unroll
    for (int off = 1; off < 4; off <<= 1) {
        cnt  += __shfl_xor_sync(0xffffffffu, cnt, off, 4);
        idxm  = min(idxm, __shfl_xor_sync(0xffffffffu, idxm, off, 4));
    }
    if (sub == 0) {
        g_m1[anchor]   = m1;
        g_cand[anchor] = (cnt == 1) ? (uint32_t)idxm : RESCAN;
    }
}

// -------- Kernel 3: per-batch key fixup + fast select + exact rank ----------
__global__ void __launch_bounds__(1024) topk_kernel(
        const float4* __restrict__ boxes,
        const float*  __restrict__ obj,
        const float*  __restrict__ cls,
        float* __restrict__ out) {
    extern __shared__ uint8_t sm[];
    unsigned long long* cand = (unsigned long long*)sm;          // 8192 B
    uint32_t* skey = (uint32_t*)(sm + 8192);                     // 33600 B
    uint32_t* hist = (uint32_t*)(sm + 8192 + 33600);             // 16384 B
    uint32_t* part = (uint32_t*)(sm + 8192 + 33600 + 16384);     // 4096 B
    __shared__ int s_valid, s_cnt, s_pivbin, s_pivcnt, s_suffnext;
    __shared__ uint32_t s_pivkey;

    int b = blockIdx.x;
    int tid = threadIdx.x;

    if (tid == 0) { s_valid = 0; s_cnt = 0; }
#pragma unroll
    for (int j = tid; j < 4096; j += 1024) hist[j] = 0;
    __syncthreads();

    // compute keys (calibrated scores) + first histogram
    int vc = 0;
    for (int i = tid; i < NA; i += 1024) {
        int gi = b * NA + i;
        float bs  = __ldg(g_beta + gi);
        float m1  = __ldg(g_m1 + gi);
        uint32_t cd = __ldg(g_cand + gi);
        float obv = __ldg(obj + gi);
        float halfbs = MULrn(0.5f, bs);
        float bestS;
        if (cd != RESCAN) {
            bestS = sigmoid_xla(SUBrn(m1, halfbs));
        } else {
            bestS = -1.0f;
            float thrW = m1 - 3e-4f;
            const float* crow = cls + (size_t)gi * NC;
            for (int c = 0; c < NC; c++) {
                float ev = __ldg(crow + c);
                if (ev > thrW) {
                    float s = sigmoid_xla(SUBrn(ev, halfbs));
                    if (s > bestS) bestS = s;
                }
            }
        }
        float so = sigmoid_xla(SUBrn(obv, bs));
        float comb = MULrn(so, bestS);
        uint32_t k = (comb >= 0.25f) ? __float_as_uint(comb) : 0u;
        skey[i] = k;
        if (k) {
            vc++;
            uint32_t bin = (k - KBASE) >> 12;
            if (bin > 4095u) bin = 4095u;
            atomicAdd(&hist[bin], 1u);
        }
    }
#pragma unroll
    for (int off = 16; off; off >>= 1) vc += __shfl_down_sync(0xffffffffu, vc, off);
    if ((tid & 31) == 0 && vc) atomicAdd(&s_valid, vc);

    // zero this batch's output region
    float* ob = out;
    float* os = out + (size_t)BATCH * KTOP * 4;
    float* oc = os + (size_t)BATCH * KTOP;
    float* ou = oc + (size_t)BATCH * KTOP;
    float* ov = ou + (size_t)BATCH * KTOP;
    for (int k = tid; k < KTOP; k += 1024) {
        ((float4*)ob)[(size_t)b * KTOP + k] = make_float4(0.f, 0.f, 0.f, 0.f);
        os[(size_t)b * KTOP + k] = 0.f;
        oc[(size_t)b * KTOP + k] = 0.f;
        ou[(size_t)b * KTOP + k] = 0.f;
        ov[(size_t)b * KTOP + k] = 0.f;
    }
    __syncthreads();

    int Kv = min(s_valid, KTOP);

    if (Kv > 0) {
        // suffix scan over 4096 bins: per-thread 4-bin sums + Hillis-Steele
        uint32_t h0 = hist[4 * tid], h1 = hist[4 * tid + 1];
        uint32_t h2 = hist[4 * tid + 2], h3 = hist[4 * tid + 3];
        uint32_t local = h0 + h1 + h2 + h3;
        part[tid] = local;
        __syncthreads();
#pragma unroll
        for (int off = 1; off < 1024; off <<= 1) {
            uint32_t t2 = (tid + off < 1024) ? part[tid + off] : 0;
            __syncthreads();
            part[tid] += t2;
            __syncthreads();
        }
        uint32_t suff0 = part[tid];
        uint32_t suff4 = (tid < 1023) ? part[tid + 1] : 0;
        uint32_t sfx[5];
        sfx[0] = suff0; sfx[1] = suff0 - h0; sfx[2] = sfx[1] - h1;
        sfx[3] = sfx[2] - h2; sfx[4] = suff4;
#pragma unroll
        for (int j = 0; j < 4; j++) {
            if (sfx[j] >= (uint32_t)Kv && sfx[j + 1] < (uint32_t)Kv) {
                s_pivbin = 4 * tid + j;
                s_pivcnt = (int)sfx[j];
                s_suffnext = (int)sfx[j + 1];
            }
        }
        __syncthreads();

        if (s_pivcnt <= 1024) {
            if (tid == 0) s_pivkey = KBASE + ((uint32_t)s_pivbin << 12);
        } else {
            // rare: refine within pivot bin on the low 12 bits
            int pb = s_pivbin;
            uint32_t base2 = KBASE + ((uint32_t)pb << 12);
            int rem2 = Kv - s_suffnext;   // rank needed inside this bin
            __syncthreads();
#pragma unroll
            for (int j = tid; j < 4096; j += 1024) hist[j] = 0;
            __syncthreads();
            for (int i = tid; i < NA; i += 1024) {
                uint32_t k = skey[i];
                if (k >= base2) {
                    uint32_t off2 = k - base2;
                    uint32_t bin2 = (off2 > 4095u) ? 4095u : off2;
                    if (((k - KBASE) >> 12) >= (uint32_t)pb)  // inside (or clamped above) pivot bin
                        if (k < base2 + 4096u || pb == 4095)
                            atomicAdd(&hist[bin2], 1u);
                }
            }
            __syncthreads();
            uint32_t g0 = hist[4 * tid], g1 = hist[4 * tid + 1];
            uint32_t g2 = hist[4 * tid + 2], g3 = hist[4 * tid + 3];
            uint32_t loc2 = g0 + g1 + g2 + g3;
            part[tid] = loc2;
            __syncthreads();
#pragma unroll
            for (int off = 1; off < 1024; off <<= 1) {
                uint32_t t2 = (tid + off < 1024) ? part[tid + off] : 0;
                __syncthreads();
                part[tid] += t2;
                __syncthreads();
            }
            uint32_t t0 = part[tid];
            uint32_t t4 = (tid < 1023) ? part[tid + 1] : 0;
            uint32_t sf2[5];
            sf2[0] = t0; sf2[1] = t0 - g0; sf2[2] = sf2[1] - g1;
            sf2[3] = sf2[2] - g2; sf2[4] = t4;
#pragma unroll
            for (int j = 0; j < 4; j++) {
                if (sf2[j] >= (uint32_t)rem2 && sf2[j + 1] < (uint32_t)rem2)
                    s_pivkey = base2 + (uint32_t)(4 * tid + j);
            }
        }
        __syncthreads();

        uint32_t pivKey = s_pivkey;
        for (int i = tid; i < NA; i += 1024) {
            uint32_t k = skey[i];
            if (k >= pivKey) {
                int p = atomicAdd(&s_cnt, 1);
                if (p < 1024)
                    cand[p] = ((unsigned long long)k << 32) | (uint32_t)(~(uint32_t)i);
            }
        }
    }
    __syncthreads();

    // exact rank-by-counting (equal keys -> lower anchor index first)
    int n = min(s_cnt, 1024);
    if (tid < n) {
        unsigned long long my = cand[tid];
        int rank = 0;
        for (int j = 0; j < n; j++) rank += (cand[j] > my);
        if (rank < Kv) {
            uint32_t key = (uint32_t)(my >> 32);
            int ai = (int)(~(uint32_t)my);
            int gi = b * NA + ai;
            // class index: stored candidate, or rare full rescan
            uint32_t cd = __ldg(g_cand + gi);
            float cl;
            if (cd != RESCAN) {
                cl = (float)cd;
            } else {
                float bs = __ldg(g_beta + gi);
                float halfbs = MULrn(0.5f, bs);
                float bestS = -1.0f; int bi = 0;
                const float* crow = cls + (size_t)gi * NC;
                for (int c = 0; c < NC; c++) {
                    float s = sigmoid_xla(SUBrn(__ldg(crow + c), halfbs));
                    if (s > bestS) { bestS = s; bi = c; }
                }
                cl = (float)bi;
            }
            ((float4*)ob)[(size_t)b * KTOP + rank] = boxes[gi];
            os[(size_t)b * KTOP + rank] = __uint_as_float(key);
            oc[(size_t)b * KTOP + rank] = cl;
            ou[(size_t)b * KTOP + rank] = __ldg(g_beta + gi);
            ov[(size_t)b * KTOP + rank] = 1.0f;
        }
    }
}

extern "C" void kernel_launch(void* const* d_in, const int* in_sizes, int n_in,
                              void* d_out, int out_size) {
    const float* boxes = nullptr;
    const float* obj   = nullptr;
    const float* cls   = nullptr;
    const float* field = nullptr;
    for (int i = 0; i < n_in; i++) {
        int s = in_sizes[i];
        if      (s == BATCH * NA * 4)      boxes = (const float*)d_in[i];
        else if (s == BATCH * NA)          obj   = (const float*)d_in[i];
        else if (s == BATCH * NA * NC)     cls   = (const float*)d_in[i];
        else if (s == BATCH * HF_ * WF_)   field = (const float*)d_in[i];
    }
    const int pool_smem = FIELD_ELEMS * 4;                      // 102.4 KB
    const int topk_smem = 8192 + 33600 + 16384 + 4096;          // 62.3 KB
    cudaFuncSetAttribute(pool_kernel, cudaFuncAttributeMaxDynamicSharedMemorySize, pool_smem);
    cudaFuncSetAttribute(topk_kernel, cudaFuncAttributeMaxDynamicSharedMemorySize, topk_smem);

    scan_kernel<<<(BATCH * NA * 4) / 256, 256>>>((const float4*)cls);
    pool_kernel<<<BATCH * POOL_SPLIT, POOL_THREADS, pool_smem>>>((const float4*)boxes, field);
    topk_kernel<<<BATCH, 1024, topk_smem>>>((const float4*)boxes, obj, cls, (float*)d_out);
}